// round 11
// baseline (speedup 1.0000x reference)
#include <cuda_runtime.h>
#include <cuda_bf16.h>

// ---------------------------------------------------------------------------
// VQ-VAE forward on GB300 (sm_103a).
// R10: weight cache capped at 64 input channels (reload 2nd half mid-loop)
// so CIN=128 stride-1 layers drop from 115.2KB -> 96.8KB smem and regain
// 2 CTAs/SM occupancy. Everything else identical to R9 (bit-exact output).
// ---------------------------------------------------------------------------

#define ULL unsigned long long

__device__ __forceinline__ ULL pack2(float a, float b) {
    ULL r; asm("mov.b64 %0, {%1, %2};" : "=l"(r) : "f"(a), "f"(b)); return r;
}
__device__ __forceinline__ void unpack2(ULL v, float& a, float& b) {
    asm("mov.b64 {%0, %1}, %2;" : "=f"(a), "=f"(b) : "l"(v));
}
__device__ __forceinline__ ULL fma2(ULL a, ULL b, ULL c) {
    ULL d; asm("fma.rn.f32x2 %0, %1, %2, %3;" : "=l"(d) : "l"(a), "l"(b), "l"(c)); return d;
}

__device__ __forceinline__ void cpa4(unsigned dst, const void* src, bool v) {
    int sz = v ? 4 : 0;
    asm volatile("cp.async.ca.shared.global [%0], [%1], 4, %2;"
                 :: "r"(dst), "l"(src), "r"(sz));
}
__device__ __forceinline__ void cpa16(unsigned dst, const void* src, bool v) {
    int sz = v ? 16 : 0;
    asm volatile("cp.async.cg.shared.global [%0], [%1], 16, %2;"
                 :: "r"(dst), "l"(src), "r"(sz));
}
__device__ __forceinline__ void cp_commit() {
    asm volatile("cp.async.commit_group;");
}
template <int N> __device__ __forceinline__ void cp_wait() {
    asm volatile("cp.async.wait_group %0;" :: "n"(N));
}

// Scratch buffers
__device__ float g_bufA[8 * 128 * 256 * 256];
__device__ float g_bufB[8 * 128 * 256 * 256];
__device__ float g_bufC[8 * 128 * 256 * 256];
__device__ float g_cbT[128 * 1024];
__device__ float g_cnorm[1024];
__device__ double g_loss;

// ---------------------------------------------------------------------------
// Stride-1 register-tiled conv, single-barrier cp.async pipeline.
// Block: 256 threads -> 64(w) x 32(h) tile, 8 output channels.
// Thread: 2x4 px as 32 f32x2 accumulators.
// Weight cache: WCI = min(CIN,64) channels; 2nd half reloaded mid-loop.
// Dynamic smem: [2 x CIB x 2448 floats][WCI x 36 ULL weights]
// ---------------------------------------------------------------------------
template <int CIN, int CIB, bool RELU, int SKIP, bool UPS>
__global__ void __launch_bounds__(256, 2) conv3x3n_k(
    const float* __restrict__ in, const float* __restrict__ wgt,
    const float* __restrict__ bias,
    const float* __restrict__ skip_in, const float* __restrict__ skip_w,
    const float* __restrict__ skip_b,
    float* __restrict__ out,
    int IH, int IW, int OH, int OW, int COUT, int CSKIP, int nG)
{
    constexpr int WCI = (CIN > 64) ? 64 : CIN;
    extern __shared__ __align__(16) char smem_raw[];
    float* tiles = (float*)smem_raw;                                   // 2*CIB*2448
    ULL* wall = (ULL*)(smem_raw + 2 * CIB * 2448 * sizeof(float));     // WCI*36

    const int t = threadIdx.x;
    const int tx = t & 15, ty = t >> 4;
    const int b = blockIdx.z / nG;
    const int co0 = (blockIdx.z - b * nG) * 8;
    const int ox0 = blockIdx.x * 64 + 4 * tx;
    const int oy0 = blockIdx.y * 32 + 2 * ty;
    const int x0a = blockIdx.x * 64 - 4;
    const int y0 = blockIdx.y * 32 - 1;
    const int DH = UPS ? IH * 2 : IH;
    const int DW = UPS ? IW * 2 : IW;

    const unsigned tiles_s = (unsigned)__cvta_generic_to_shared(tiles);

    auto stage = [&](int ci0, int buf) {
        unsigned tb = tiles_s + buf * (CIB * 2448 * 4);
        if (!UPS) {
            constexpr int NCH = CIB * 612;    // 34 rows x 18 chunks per channel
#pragma unroll
            for (int j = 0; j < (NCH + 255) / 256; j++) {
                int e = t + 256 * j;
                if (e < NCH) {
                    int ci_l = e / 612, rem = e - ci_l * 612;
                    int row = rem / 18, c16 = rem - row * 18;
                    int gy = y0 + row;
                    int gx = x0a + 4 * c16;
                    bool v = (unsigned)gy < (unsigned)IH && (unsigned)gx < (unsigned)IW;
                    const float* inc = in + (b * CIN + ci0 + ci_l) * (IH * IW);
                    const float* sp = inc + (v ? (gy * IW + gx) : 0);
                    cpa16(tb + (ci_l * 2448 + row * 72 + 4 * c16) * 4, sp, v);
                }
            }
        } else {
            constexpr int NSC = CIB * 2448;   // scalar path (nearest-2x gather)
#pragma unroll
            for (int j = 0; j < (NSC + 255) / 256; j++) {
                int e = t + 256 * j;
                if (e < NSC) {
                    int ci_l = e / 2448, rem = e - ci_l * 2448;
                    int row = rem / 72, col = rem - row * 72;
                    int gy = y0 + row, gx = x0a + col;
                    bool v = (unsigned)gy < (unsigned)DH && (unsigned)gx < (unsigned)DW;
                    int iy = gy >> 1, ix = gx >> 1;
                    const float* inc = in + (b * CIN + ci0 + ci_l) * (IH * IW);
                    const float* sp = inc + (v ? (iy * IW + ix) : 0);
                    cpa4(tb + (ci_l * 2448 + rem) * 4, sp, v);
                }
            }
        }
        cp_commit();
    };

    // load weight pairs for WCI channels starting at cbase:
    // wall[ci_l*36 + k*4 + p] = (w[co0+2p][cbase+ci_l][k], w[co0+2p+1][...])
    auto load_wall = [&](int cbase) {
        for (int e = t; e < WCI * 36; e += 256) {
            int ci_l = e / 36, r = e - ci_l * 36;
            int k = r >> 2, p = r & 3;
            int ca = co0 + 2 * p;
            int ci = cbase + ci_l;
            float wa = (ca < COUT) ? wgt[(ca * CIN + ci) * 9 + k] : 0.f;
            float wb = (ca + 1 < COUT) ? wgt[((ca + 1) * CIN + ci) * 9 + k] : 0.f;
            wall[e] = pack2(wa, wb);
        }
    };

    ULL acc[2][4][4];
#pragma unroll
    for (int py = 0; py < 2; py++)
#pragma unroll
        for (int px = 0; px < 4; px++)
#pragma unroll
            for (int p = 0; p < 4; p++) acc[py][px][p] = 0ull;

    constexpr int NR = CIN / CIB;
    stage(0, 0);
    load_wall(0);

    // single-barrier pipeline; mid-loop weight reload for CIN > 64.
#pragma unroll 1
    for (int i = 0; i < NR; i++) {
        cp_wait<0>();
        __syncthreads();
        if (CIN > WCI && i * CIB == WCI) {
            load_wall(WCI);
            __syncthreads();
        }
        if (i + 1 < NR) stage((i + 1) * CIB, (i + 1) & 1);
        const float* tbuf = tiles + (i & 1) * (CIB * 2448);
#pragma unroll
        for (int ci_l = 0; ci_l < CIB; ci_l++) {
            const float* tci = tbuf + ci_l * 2448;
            // rv[r][j] <-> tile col 4tx+3+j <-> gx = blk*64 - 1 + 4tx + j
            float rv[4][6];
#pragma unroll
            for (int r = 0; r < 4; r++) {
                const float* p = &tci[(2 * ty + r) * 72 + 4 * tx];
                float4 a = *(const float4*)p;
                float4 b4 = *(const float4*)(p + 4);
                rv[r][0] = a.w;
                rv[r][1] = b4.x; rv[r][2] = b4.y; rv[r][3] = b4.z; rv[r][4] = b4.w;
                rv[r][5] = p[8];
            }
            const int wci = (i * CIB + ci_l) & (WCI > 1 ? (WCI == 64 ? 63 : 0x7fffffff) : 0);
            const ulonglong2* wsc = (const ulonglong2*)(wall +
                ((CIN > 64) ? ((i * CIB + ci_l) & 63) : (i * CIB + ci_l)) * 36);
            (void)wci;
#pragma unroll
            for (int ky = 0; ky < 3; ky++) {
#pragma unroll
                for (int kx = 0; kx < 3; kx++) {
                    const int k = ky * 3 + kx;
                    ulonglong2 wA = wsc[k * 2];
                    ulonglong2 wB = wsc[k * 2 + 1];
#pragma unroll
                    for (int py = 0; py < 2; py++) {
#pragma unroll
                        for (int px = 0; px < 4; px++) {
                            float v = rv[py + ky][px + kx];
                            ULL vv = pack2(v, v);
                            acc[py][px][0] = fma2(vv, wA.x, acc[py][px][0]);
                            acc[py][px][1] = fma2(vv, wA.y, acc[py][px][1]);
                            acc[py][px][2] = fma2(vv, wB.x, acc[py][px][2]);
                            acc[py][px][3] = fma2(vv, wB.y, acc[py][px][3]);
                        }
                    }
                }
            }
        }
    }

    // fused 1x1-conv skip, 4 cs channels per sync round
    if (SKIP == 2) {
        __syncthreads();   // release tile buffers from last compute round
#pragma unroll 1
        for (int cs0 = 0; cs0 < CSKIP; cs0 += 4) {
#pragma unroll
            for (int cs_l = 0; cs_l < 4; cs_l++) {
                const float* sp = skip_in + (b * CSKIP + cs0 + cs_l) * OH * OW
                                + (blockIdx.y * 32) * OW + blockIdx.x * 64;
#pragma unroll
                for (int j = 0; j < 8; j++) {
                    int i = t + 256 * j;
                    int row = i >> 6, col = i & 63;
                    tiles[cs_l * 2048 + i] = sp[row * OW + col];
                }
            }
            if (t < 16) {
                int cs_l = t >> 2, p = t & 3;
                int ca = co0 + 2 * p;
                float wa = (ca < COUT) ? skip_w[ca * CSKIP + cs0 + cs_l] : 0.f;
                float wb = (ca + 1 < COUT) ? skip_w[(ca + 1) * CSKIP + cs0 + cs_l] : 0.f;
                wall[t] = pack2(wa, wb);
            }
            __syncthreads();
#pragma unroll
            for (int cs_l = 0; cs_l < 4; cs_l++) {
                ulonglong2 wA = ((const ulonglong2*)wall)[cs_l * 2];
                ulonglong2 wB = ((const ulonglong2*)wall)[cs_l * 2 + 1];
#pragma unroll
                for (int py = 0; py < 2; py++) {
                    float4 s4 = *(const float4*)&tiles[cs_l * 2048 + (2 * ty + py) * 64 + 4 * tx];
                    float sv[4] = {s4.x, s4.y, s4.z, s4.w};
#pragma unroll
                    for (int px = 0; px < 4; px++) {
                        ULL vv = pack2(sv[px], sv[px]);
                        acc[py][px][0] = fma2(vv, wA.x, acc[py][px][0]);
                        acc[py][px][1] = fma2(vv, wA.y, acc[py][px][1]);
                        acc[py][px][2] = fma2(vv, wB.x, acc[py][px][2]);
                        acc[py][px][3] = fma2(vv, wB.y, acc[py][px][3]);
                    }
                }
            }
            __syncthreads();
        }
    }

    // epilogue: bias (+skip) (+relu), float4 stores
    float bv[8];
#pragma unroll
    for (int c = 0; c < 8; c++) bv[c] = (co0 + c < COUT) ? bias[co0 + c] : 0.f;

#pragma unroll
    for (int c = 0; c < 8; c++) {
        const int co = co0 + c;
        if (co < COUT) {
            const int p = c >> 1, hi = c & 1;
#pragma unroll
            for (int py = 0; py < 2; py++) {
                float o[4];
#pragma unroll
                for (int px = 0; px < 4; px++) {
                    float a0, a1;
                    unpack2(acc[py][px][p], a0, a1);
                    o[px] = (hi ? a1 : a0) + bv[c];
                }
                const int base = ((b * COUT + co) * OH + oy0 + py) * OW + ox0;
                if (SKIP == 1) {
                    float4 s = *(const float4*)&skip_in[base];
                    o[0] += s.x; o[1] += s.y; o[2] += s.z; o[3] += s.w;
                }
                if (SKIP == 2) {
                    float sb = skip_b[co];
#pragma unroll
                    for (int px = 0; px < 4; px++) o[px] += sb;
                }
                if (RELU) {
#pragma unroll
                    for (int px = 0; px < 4; px++) o[px] = fmaxf(o[px], 0.f);
                }
                float4 ov; ov.x = o[0]; ov.y = o[1]; ov.z = o[2]; ov.w = o[3];
                *(float4*)&out[base] = ov;
            }
        }
    }
}

// ---------------------------------------------------------------------------
// Stride-2 conv (relu, no skip), single-barrier cp.async pipeline.
// Weight cache also capped at 64 channels (same mid-loop reload).
// Dynamic smem: [2 x CIB x 4680 floats][64 x 36 ULL]
// ---------------------------------------------------------------------------
template <int CIN, int CIB>
__global__ void __launch_bounds__(256, 2) conv3x3s2_k(
    const float* __restrict__ in, const float* __restrict__ wgt,
    const float* __restrict__ bias, float* __restrict__ out,
    int IH, int IW, int OH, int OW, int COUT, int nG)
{
    constexpr int WCI = (CIN > 64) ? 64 : CIN;
    extern __shared__ __align__(16) char smem_raw[];
    float* tiles = (float*)smem_raw;                                   // 2*CIB*4680
    ULL* wall = (ULL*)(smem_raw + 2 * CIB * 4680 * sizeof(float));     // WCI*36

    const int t = threadIdx.x;
    const int tx = t & 15, ty = t >> 4;
    const int b = blockIdx.z / nG;
    const int co0 = (blockIdx.z - b * nG) * 8;
    const int ox0 = blockIdx.x * 32;
    const int oy0 = blockIdx.y * 32;
    const int x0a = blockIdx.x * 64 - 4;
    const int y0 = blockIdx.y * 64 - 1;

    const unsigned tiles_s = (unsigned)__cvta_generic_to_shared(tiles);

    auto stage = [&](int ci0, int buf) {
        unsigned tb = tiles_s + buf * (CIB * 4680 * 4);
        constexpr int NCH = CIB * 1170;   // 65 rows x 18 chunks
#pragma unroll
        for (int j = 0; j < (NCH + 255) / 256; j++) {
            int e = t + 256 * j;
            if (e < NCH) {
                int ci_l = e / 1170, rem = e - ci_l * 1170;
                int row = rem / 18, c16 = rem - row * 18;
                int gy = y0 + row;
                int gx = x0a + 4 * c16;
                bool v = (unsigned)gy < (unsigned)IH && (unsigned)gx < (unsigned)IW;
                const float* inc = in + (b * CIN + ci0 + ci_l) * (IH * IW);
                const float* sp = inc + (v ? (gy * IW + gx) : 0);
                cpa16(tb + (ci_l * 4680 + row * 72 + 4 * c16) * 4, sp, v);
            }
        }
        cp_commit();
    };

    auto load_wall = [&](int cbase) {
        for (int e = t; e < WCI * 36; e += 256) {
            int ci_l = e / 36, r = e - ci_l * 36;
            int k = r >> 2, p = r & 3;
            int ca = co0 + 2 * p;
            int ci = cbase + ci_l;
            float wa = (ca < COUT) ? wgt[(ca * CIN + ci) * 9 + k] : 0.f;
            float wb = (ca + 1 < COUT) ? wgt[((ca + 1) * CIN + ci) * 9 + k] : 0.f;
            wall[e] = pack2(wa, wb);
        }
    };

    ULL acc[2][2][4];
#pragma unroll
    for (int py = 0; py < 2; py++)
#pragma unroll
        for (int px = 0; px < 2; px++)
#pragma unroll
            for (int p = 0; p < 4; p++) acc[py][px][p] = 0ull;

    constexpr int NR = CIN / CIB;
    stage(0, 0);
    load_wall(0);

#pragma unroll 1
    for (int i = 0; i < NR; i++) {
        cp_wait<0>();
        __syncthreads();
        if (CIN > WCI && i * CIB == WCI) {
            load_wall(WCI);
            __syncthreads();
        }
        if (i + 1 < NR) stage((i + 1) * CIB, (i + 1) & 1);
        const float* tbuf = tiles + (i & 1) * (CIB * 4680);
#pragma unroll
        for (int ci_l = 0; ci_l < CIB; ci_l++) {
            const float* tci = tbuf + ci_l * 4680;
            float rv[5][5];
#pragma unroll
            for (int r = 0; r < 5; r++) {
                const float* p = &tci[(4 * ty + r) * 72 + 4 * tx];
                float4 a = *(const float4*)p;
                float4 b4 = *(const float4*)(p + 4);
                rv[r][0] = a.w;
                rv[r][1] = b4.x; rv[r][2] = b4.y; rv[r][3] = b4.z; rv[r][4] = b4.w;
            }
            const ulonglong2* wsc = (const ulonglong2*)(wall +
                ((CIN > 64) ? ((i * CIB + ci_l) & 63) : (i * CIB + ci_l)) * 36);
#pragma unroll
            for (int ky = 0; ky < 3; ky++) {
#pragma unroll
                for (int kx = 0; kx < 3; kx++) {
                    const int k = ky * 3 + kx;
                    ulonglong2 wA = wsc[k * 2];
                    ulonglong2 wB = wsc[k * 2 + 1];
#pragma unroll
                    for (int py = 0; py < 2; py++) {
#pragma unroll
                        for (int px = 0; px < 2; px++) {
                            float v = rv[2 * py + ky][2 * px + kx];
                            ULL vv = pack2(v, v);
                            acc[py][px][0] = fma2(vv, wA.x, acc[py][px][0]);
                            acc[py][px][1] = fma2(vv, wA.y, acc[py][px][1]);
                            acc[py][px][2] = fma2(vv, wB.x, acc[py][px][2]);
                            acc[py][px][3] = fma2(vv, wB.y, acc[py][px][3]);
                        }
                    }
                }
            }
        }
    }

#pragma unroll
    for (int c = 0; c < 8; c++) {
        const int co = co0 + c;
        if (co < COUT) {
            const float bb = bias[co];
            const int p = c >> 1, hi = c & 1;
#pragma unroll
            for (int py = 0; py < 2; py++) {
                float o[2];
#pragma unroll
                for (int px = 0; px < 2; px++) {
                    float a0, a1;
                    unpack2(acc[py][px][p], a0, a1);
                    o[px] = fmaxf((hi ? a1 : a0) + bb, 0.f);
                }
                float2 ov; ov.x = o[0]; ov.y = o[1];
                *(float2*)&out[((b * COUT + co) * OH + oy0 + 2 * ty + py) * OW
                               + ox0 + 2 * tx] = ov;
            }
        }
    }
}

// ---------------------------------------------------------------------------
// XLA-style warp row reduction of sum(x*x) over 128 elements.
// ---------------------------------------------------------------------------
__device__ __forceinline__ float warp_sumsq_128(const float* __restrict__ x, int lane)
{
    float s = 0.f;
#pragma unroll
    for (int i = 0; i < 4; i++) {
        float v = x[lane + 32 * i];
        s = __fadd_rn(s, __fmul_rn(v, v));
    }
#pragma unroll
    for (int off = 16; off > 0; off >>= 1)
        s = __fadd_rn(s, __shfl_down_sync(0xffffffffu, s, off));
    return s;
}

__global__ void __launch_bounds__(256) prep_cnorm_k(const float* __restrict__ cb)
{
    if (blockIdx.x == 0 && threadIdx.x == 0) g_loss = 0.0;
    int warp = (blockIdx.x * 256 + threadIdx.x) >> 5;
    int lane = threadIdx.x & 31;
    if (warp < 1024) {
        float s = warp_sumsq_128(cb + warp * 128, lane);
        if (lane == 0) g_cnorm[warp] = s;
    }
}

__global__ void __launch_bounds__(256) transpose_cb_k(const float* __restrict__ cb)
{
    int i = blockIdx.x * 256 + threadIdx.x;
    int code = i >> 7, k = i & 127;
    g_cbT[k * 1024 + code] = cb[i];
}

// ---------------------------------------------------------------------------
// Quantizer (unchanged — arithmetic is load-bearing):
// d = fl( fl(znorm - 2*dot) + cnorm ), sequential-k fp32 FMA chains,
// lexicographic argmin, straight-through fl(z + fl(q - z)).
// ---------------------------------------------------------------------------
__global__ void __launch_bounds__(256) quantize_k(
    const float* __restrict__ z, const float* __restrict__ cb,
    float* __restrict__ qst)
{
    __shared__ float ct[8 * 1024];
    __shared__ float zs[16 * 128];
    __shared__ float znorm_s[16];
    __shared__ float cand_d[16][8];
    __shared__ int   cand_i[16][8];
    __shared__ int   kbest_s[16];
    __shared__ double red[256];

    const int t = threadIdx.x;
    const int lane = t & 31, w = t >> 5;
    const long long row0 = (long long)blockIdx.x * 16;

    {
        const float4* zg = (const float4*)(z + row0 * 128);
        float4* z4 = (float4*)zs;
#pragma unroll
        for (int j = 0; j < 2; j++) z4[t + 256 * j] = zg[t + 256 * j];
    }
    __syncthreads();

#pragma unroll
    for (int rr = 0; rr < 2; rr++) {
        int r = w + 8 * rr;
        float s = warp_sumsq_128(zs + r * 128, lane);
        if (lane == 0) znorm_s[r] = s;
    }

    ULL acc[16][2];
#pragma unroll
    for (int r = 0; r < 16; r++) { acc[r][0] = 0ull; acc[r][1] = 0ull; }

#pragma unroll 1
    for (int kt = 0; kt < 16; kt++) {
        __syncthreads();
        {
            const float4* gt = (const float4*)(g_cbT + kt * 8 * 1024);
            float4* c4s = (float4*)ct;
#pragma unroll
            for (int j = 0; j < 8; j++) c4s[t + 256 * j] = gt[t + 256 * j];
        }
        __syncthreads();
#pragma unroll
        for (int kk = 0; kk < 8; kk++) {
            float4 c4 = ((const float4*)ct)[kk * 256 + t];
            ULL cab = pack2(c4.x, c4.y);
            ULL ccd = pack2(c4.z, c4.w);
            const int k = kt * 8 + kk;
#pragma unroll
            for (int r = 0; r < 16; r++) {
                float zk = zs[r * 128 + k];
                ULL zz = pack2(zk, zk);
                acc[r][0] = fma2(zz, cab, acc[r][0]);
                acc[r][1] = fma2(zz, ccd, acc[r][1]);
            }
        }
    }
    __syncthreads();

    float4 cn4 = *(const float4*)(g_cnorm + 4 * t);
#pragma unroll
    for (int r = 0; r < 16; r++) {
        float a, b, c, d;
        unpack2(acc[r][0], a, b);
        unpack2(acc[r][1], c, d);
        float zn = znorm_s[r];
        float d0 = __fadd_rn(__fsub_rn(zn, __fmul_rn(2.f, a)), cn4.x);
        float d1 = __fadd_rn(__fsub_rn(zn, __fmul_rn(2.f, b)), cn4.y);
        float d2 = __fadd_rn(__fsub_rn(zn, __fmul_rn(2.f, c)), cn4.z);
        float d3 = __fadd_rn(__fsub_rn(zn, __fmul_rn(2.f, d)), cn4.w);
        float bv = d0; int bi = 4 * t;
        if (d1 < bv) { bv = d1; bi = 4 * t + 1; }
        if (d2 < bv) { bv = d2; bi = 4 * t + 2; }
        if (d3 < bv) { bv = d3; bi = 4 * t + 3; }
#pragma unroll
        for (int off = 16; off > 0; off >>= 1) {
            float ov = __shfl_down_sync(0xffffffffu, bv, off);
            int   oi = __shfl_down_sync(0xffffffffu, bi, off);
            if (ov < bv || (ov == bv && oi < bi)) { bv = ov; bi = oi; }
        }
        if (lane == 0) { cand_d[r][w] = bv; cand_i[r][w] = bi; }
    }
    __syncthreads();
    if (t < 16) {
        float bv = cand_d[t][0]; int bi = cand_i[t][0];
#pragma unroll
        for (int j = 1; j < 8; j++) {
            float ov = cand_d[t][j]; int oi = cand_i[t][j];
            if (ov < bv || (ov == bv && oi < bi)) { bv = ov; bi = oi; }
        }
        kbest_s[t] = bi;
    }
    __syncthreads();

    double ls = 0.0;
#pragma unroll
    for (int j = 0; j < 8; j++) {
        int e = j * 256 + t;
        int r = e >> 7, col = e & 127;
        float zv = zs[r * 128 + col];
        float qv = cb[kbest_s[r] * 128 + col];
        float qz = __fsub_rn(qv, zv);
        float st = __fadd_rn(zv, qz);
        qst[(row0 + r) * 128 + col] = st;
        ls += (double)qz * (double)qz;
    }
    red[t] = ls;
    __syncthreads();
    for (int s = 128; s > 0; s >>= 1) {
        if (t < s) red[t] += red[t + s];
        __syncthreads();
    }
    if (t == 0) atomicAdd(&g_loss, red[0]);
}

__global__ void finish_k(float* __restrict__ out, int start, int total)
{
    float v = (float)(1.25 * g_loss / 16777216.0);
    for (int i = start + threadIdx.x; i < total; i += 32) out[i] = v;
}

// ---------------------------------------------------------------------------
extern "C" void kernel_launch(void* const* d_in, const int* in_sizes, int n_in,
                              void* d_out, int out_size)
{
    const float* x          = (const float*)d_in[0];
    const float* enc_in_w   = (const float*)d_in[1];
    const float* enc_in_b   = (const float*)d_in[2];
    const float* rb0_w1     = (const float*)d_in[3];
    const float* rb0_b1     = (const float*)d_in[4];
    const float* rb0_w2     = (const float*)d_in[5];
    const float* rb0_b2     = (const float*)d_in[6];
    const float* rb1_w1     = (const float*)d_in[7];
    const float* rb1_b1     = (const float*)d_in[8];
    const float* rb1_w2     = (const float*)d_in[9];
    const float* rb1_b2     = (const float*)d_in[10];
    const float* rb1_ws     = (const float*)d_in[11];
    const float* rb1_bs     = (const float*)d_in[12];
    const float* down_w     = (const float*)d_in[13];
    const float* down_b     = (const float*)d_in[14];
    const float* codebook   = (const float*)d_in[15];
    const float* d1_w1      = (const float*)d_in[16];
    const float* d1_b1      = (const float*)d_in[17];
    const float* d1_w2      = (const float*)d_in[18];
    const float* d1_b2      = (const float*)d_in[19];
    const float* up_w       = (const float*)d_in[20];
    const float* up_b       = (const float*)d_in[21];
    const float* d0_w1      = (const float*)d_in[22];
    const float* d0_b1      = (const float*)d_in[23];
    const float* d0_w2      = (const float*)d_in[24];
    const float* d0_b2      = (const float*)d_in[25];
    const float* out_w      = (const float*)d_in[26];
    const float* out_b      = (const float*)d_in[27];
    float* out = (float*)d_out;

    float *bufA, *bufB, *bufC;
    cudaGetSymbolAddress((void**)&bufA, g_bufA);
    cudaGetSymbolAddress((void**)&bufB, g_bufB);
    cudaGetSymbolAddress((void**)&bufC, g_bufC);

    // dynamic smem: tiles 2*CIB*2448*4 + weights min(CIN,64)*36*8
    const int SM_3   = 2 * 3 * 2448 * 4 + 3 * 36 * 8;     //  59616
    const int SM_64  = 2 * 4 * 2448 * 4 + 64 * 36 * 8;    //  96768
    const int SM_128 = 2 * 4 * 2448 * 4 + 64 * 36 * 8;    //  96768 (2 CTAs now)
    const int SM_S2  = 2 * 2 * 4680 * 4 + 64 * 36 * 8;    //  93312

    cudaFuncSetAttribute(conv3x3n_k<3, 3, false, 0, false>,  cudaFuncAttributeMaxDynamicSharedMemorySize, SM_3);
    cudaFuncSetAttribute(conv3x3n_k<64, 4, true, 0, false>,  cudaFuncAttributeMaxDynamicSharedMemorySize, SM_64);
    cudaFuncSetAttribute(conv3x3n_k<64, 4, true, 1, false>,  cudaFuncAttributeMaxDynamicSharedMemorySize, SM_64);
    cudaFuncSetAttribute(conv3x3n_k<64, 4, false, 0, false>, cudaFuncAttributeMaxDynamicSharedMemorySize, SM_64);
    cudaFuncSetAttribute(conv3x3n_k<128, 4, true, 0, false>, cudaFuncAttributeMaxDynamicSharedMemorySize, SM_128);
    cudaFuncSetAttribute(conv3x3n_k<128, 4, true, 1, false>, cudaFuncAttributeMaxDynamicSharedMemorySize, SM_128);
    cudaFuncSetAttribute(conv3x3n_k<128, 4, true, 2, false>, cudaFuncAttributeMaxDynamicSharedMemorySize, SM_128);
    cudaFuncSetAttribute(conv3x3n_k<128, 4, true, 0, true>,  cudaFuncAttributeMaxDynamicSharedMemorySize, SM_128);
    cudaFuncSetAttribute(conv3x3s2_k<128, 2>,                cudaFuncAttributeMaxDynamicSharedMemorySize, SM_S2);

    const int B = 8;
    dim3 G256_64(4, 8, B * 8);
    dim3 G256_128(4, 8, B * 16);
    dim3 G128_128(2, 4, B * 16);
    dim3 G256_3(4, 8, B * 1);
    dim3 GS2(4, 4, B * 16);

    transpose_cb_k<<<512, 256>>>(codebook);
    prep_cnorm_k<<<128, 256>>>(codebook);

    // ---- encoder ----
    conv3x3n_k<3, 3, false, 0, false><<<G256_64, 256, SM_3>>>(
        x, enc_in_w, enc_in_b, nullptr, nullptr, nullptr, bufA,
        256, 256, 256, 256, 64, 0, 8);
    conv3x3n_k<64, 4, true, 0, false><<<G256_64, 256, SM_64>>>(
        bufA, rb0_w1, rb0_b1, nullptr, nullptr, nullptr, bufB,
        256, 256, 256, 256, 64, 0, 8);
    conv3x3n_k<64, 4, true, 1, false><<<G256_64, 256, SM_64>>>(
        bufB, rb0_w2, rb0_b2, bufA, nullptr, nullptr, bufC,
        256, 256, 256, 256, 64, 0, 8);
    conv3x3n_k<64, 4, true, 0, false><<<G256_128, 256, SM_64>>>(
        bufC, rb1_w1, rb1_b1, nullptr, nullptr, nullptr, bufA,
        256, 256, 256, 256, 128, 0, 16);
    conv3x3n_k<128, 4, true, 2, false><<<G256_128, 256, SM_128>>>(
        bufA, rb1_w2, rb1_b2, bufC, rb1_ws, rb1_bs, bufB,
        256, 256, 256, 256, 128, 64, 16);
    conv3x3s2_k<128, 2><<<GS2, 256, SM_S2>>>(
        bufB, down_w, down_b, bufC,
        256, 256, 128, 128, 128, 16);

    // ---- quantizer ----
    quantize_k<<<8192, 256>>>(bufC, codebook, bufA);

    // ---- decoder ----
    conv3x3n_k<128, 4, true, 0, false><<<G128_128, 256, SM_128>>>(
        bufA, d1_w1, d1_b1, nullptr, nullptr, nullptr, bufB,
        128, 128, 128, 128, 128, 0, 16);
    conv3x3n_k<128, 4, true, 1, false><<<G128_128, 256, SM_128>>>(
        bufB, d1_w2, d1_b2, bufA, nullptr, nullptr, bufC,
        128, 128, 128, 128, 128, 0, 16);
    conv3x3n_k<128, 4, true, 0, true><<<G256_64, 256, SM_128>>>(
        bufC, up_w, up_b, nullptr, nullptr, nullptr, bufA,
        128, 128, 256, 256, 64, 0, 8);
    conv3x3n_k<64, 4, true, 0, false><<<G256_64, 256, SM_64>>>(
        bufA, d0_w1, d0_b1, nullptr, nullptr, nullptr, bufB,
        256, 256, 256, 256, 64, 0, 8);
    conv3x3n_k<64, 4, true, 1, false><<<G256_64, 256, SM_64>>>(
        bufB, d0_w2, d0_b2, bufA, nullptr, nullptr, bufC,
        256, 256, 256, 256, 64, 0, 8);
    conv3x3n_k<64, 4, false, 0, false><<<G256_3, 256, SM_64>>>(
        bufC, out_w, out_b, nullptr, nullptr, nullptr, out,
        256, 256, 256, 256, 3, 0, 1);

    const int recon = 8 * 3 * 256 * 256;
    if (out_size > recon) finish_k<<<1, 32>>>(out, recon, out_size);
}

// round 12
// speedup vs baseline: 1.0311x; 1.0311x over previous
#include <cuda_runtime.h>
#include <cuda_bf16.h>

// ---------------------------------------------------------------------------
// VQ-VAE forward on GB300 (sm_103a).
// R12: UPS layer staged at source resolution (vectorized 16B cp.async,
// nearest-2x duplication done in registers); fused 1x1-skip batched 8/round
// with float4 staging. FMA chain order unchanged -> bit-identical output.
// ---------------------------------------------------------------------------

#define ULL unsigned long long

__device__ __forceinline__ ULL pack2(float a, float b) {
    ULL r; asm("mov.b64 %0, {%1, %2};" : "=l"(r) : "f"(a), "f"(b)); return r;
}
__device__ __forceinline__ void unpack2(ULL v, float& a, float& b) {
    asm("mov.b64 {%0, %1}, %2;" : "=f"(a), "=f"(b) : "l"(v));
}
__device__ __forceinline__ ULL fma2(ULL a, ULL b, ULL c) {
    ULL d; asm("fma.rn.f32x2 %0, %1, %2, %3;" : "=l"(d) : "l"(a), "l"(b), "l"(c)); return d;
}

__device__ __forceinline__ void cpa16(unsigned dst, const void* src, bool v) {
    int sz = v ? 16 : 0;
    asm volatile("cp.async.cg.shared.global [%0], [%1], 16, %2;"
                 :: "r"(dst), "l"(src), "r"(sz));
}
__device__ __forceinline__ void cp_commit() {
    asm volatile("cp.async.commit_group;");
}
template <int N> __device__ __forceinline__ void cp_wait() {
    asm volatile("cp.async.wait_group %0;" :: "n"(N));
}

// Scratch buffers
__device__ float g_bufA[8 * 128 * 256 * 256];
__device__ float g_bufB[8 * 128 * 256 * 256];
__device__ float g_bufC[8 * 128 * 256 * 256];
__device__ float g_cbT[128 * 1024];
__device__ float g_cnorm[1024];
__device__ double g_loss;

// ---------------------------------------------------------------------------
// Stride-1 register-tiled conv, single-barrier cp.async pipeline.
// Block: 256 threads -> 64(w) x 32(h) tile, 8 output channels.
// Thread: 2x4 px as 32 f32x2 accumulators.
// Non-UPS tile: 34 rows x 72-float stride, frame col0 <-> gx = blkX*64 - 4.
// UPS tile: source-res, 18 rows x 40-float stride, col0 <-> ix = blkX*32 - 4;
//           duplication applied in registers at rv-load (bit-identical values).
// Weight cache: WCI = min(CIN,64) channels; 2nd half reloaded mid-loop.
// ---------------------------------------------------------------------------
template <int CIN, int CIB, bool RELU, int SKIP, bool UPS>
__global__ void __launch_bounds__(256, 2) conv3x3n_k(
    const float* __restrict__ in, const float* __restrict__ wgt,
    const float* __restrict__ bias,
    const float* __restrict__ skip_in, const float* __restrict__ skip_w,
    const float* __restrict__ skip_b,
    float* __restrict__ out,
    int IH, int IW, int OH, int OW, int COUT, int CSKIP, int nG)
{
    constexpr int WCI = (CIN > 64) ? 64 : CIN;
    constexpr int TCI = UPS ? 720 : 2448;     // floats per channel tile
    extern __shared__ __align__(16) char smem_raw[];
    float* tiles = (float*)smem_raw;                                   // 2*CIB*TCI
    ULL* wall = (ULL*)(smem_raw + 2 * CIB * TCI * sizeof(float));      // WCI*36

    const int t = threadIdx.x;
    const int tx = t & 15, ty = t >> 4;
    const int b = blockIdx.z / nG;
    const int co0 = (blockIdx.z - b * nG) * 8;
    const int ox0 = blockIdx.x * 64 + 4 * tx;
    const int oy0 = blockIdx.y * 32 + 2 * ty;
    const int x0a = blockIdx.x * 64 - 4;      // non-UPS frame origin (gx)
    const int y0 = blockIdx.y * 32 - 1;
    const int iy_base = y0 >> 1;              // UPS: source row of tile row 0
    const int ix_base = blockIdx.x * 32 - 4;  // UPS: source col of tile col 0

    const unsigned tiles_s = (unsigned)__cvta_generic_to_shared(tiles);

    auto stage = [&](int ci0, int buf) {
        unsigned tb = tiles_s + buf * (CIB * TCI * 4);
        if (!UPS) {
            constexpr int NCH = CIB * 612;    // 34 rows x 18 chunks per channel
#pragma unroll
            for (int j = 0; j < (NCH + 255) / 256; j++) {
                int e = t + 256 * j;
                if (e < NCH) {
                    int ci_l = e / 612, rem = e - ci_l * 612;
                    int row = rem / 18, c16 = rem - row * 18;
                    int gy = y0 + row;
                    int gx = x0a + 4 * c16;
                    bool v = (unsigned)gy < (unsigned)IH && (unsigned)gx < (unsigned)IW;
                    const float* inc = in + (b * CIN + ci0 + ci_l) * (IH * IW);
                    const float* sp = inc + (v ? (gy * IW + gx) : 0);
                    cpa16(tb + (ci_l * 2448 + row * 72 + 4 * c16) * 4, sp, v);
                }
            }
        } else {
            constexpr int NCH = CIB * 180;    // 18 rows x 10 chunks per channel
#pragma unroll
            for (int j = 0; j < (NCH + 255) / 256; j++) {
                int e = t + 256 * j;
                if (e < NCH) {
                    int ci_l = e / 180, rem = e - ci_l * 180;
                    int row = rem / 10, c16 = rem - row * 10;
                    int iy = iy_base + row;
                    int ix = ix_base + 4 * c16;
                    bool v = (unsigned)iy < (unsigned)IH && (unsigned)ix < (unsigned)IW;
                    const float* inc = in + (b * CIN + ci0 + ci_l) * (IH * IW);
                    const float* sp = inc + (v ? (iy * IW + ix) : 0);
                    cpa16(tb + (ci_l * 720 + row * 40 + 4 * c16) * 4, sp, v);
                }
            }
        }
        cp_commit();
    };

    auto load_wall = [&](int cbase) {
        for (int e = t; e < WCI * 36; e += 256) {
            int ci_l = e / 36, r = e - ci_l * 36;
            int k = r >> 2, p = r & 3;
            int ca = co0 + 2 * p;
            int ci = cbase + ci_l;
            float wa = (ca < COUT) ? wgt[(ca * CIN + ci) * 9 + k] : 0.f;
            float wb = (ca + 1 < COUT) ? wgt[((ca + 1) * CIN + ci) * 9 + k] : 0.f;
            wall[e] = pack2(wa, wb);
        }
    };

    ULL acc[2][4][4];
#pragma unroll
    for (int py = 0; py < 2; py++)
#pragma unroll
        for (int px = 0; px < 4; px++)
#pragma unroll
            for (int p = 0; p < 4; p++) acc[py][px][p] = 0ull;

    constexpr int NR = CIN / CIB;
    stage(0, 0);
    load_wall(0);

#pragma unroll 1
    for (int i = 0; i < NR; i++) {
        cp_wait<0>();
        __syncthreads();
        if (CIN > WCI && i * CIB == WCI) {
            load_wall(WCI);
            __syncthreads();
        }
        if (i + 1 < NR) stage((i + 1) * CIB, (i + 1) & 1);
        const float* tbuf = tiles + (i & 1) * (CIB * TCI);
#pragma unroll
        for (int ci_l = 0; ci_l < CIB; ci_l++) {
            const float* tci = tbuf + ci_l * TCI;
            // rv[r][j] <-> conv-domain gx = blk*64 - 1 + 4tx + j, gy = y0 + 2ty + r
            float rv[4][6];
            if (!UPS) {
#pragma unroll
                for (int r = 0; r < 4; r++) {
                    const float* p = &tci[(2 * ty + r) * 72 + 4 * tx];
                    float4 a = *(const float4*)p;
                    float4 b4 = *(const float4*)(p + 4);
                    rv[r][0] = a.w;
                    rv[r][1] = b4.x; rv[r][2] = b4.y; rv[r][3] = b4.z; rv[r][4] = b4.w;
                    rv[r][5] = p[8];
                }
            } else {
                // source rows ty..ty+2, source cols 2tx+3..2tx+6
                float s[3][4];
#pragma unroll
                for (int rr = 0; rr < 3; rr++)
#pragma unroll
                    for (int cc = 0; cc < 4; cc++)
                        s[rr][cc] = tci[(ty + rr) * 40 + 2 * tx + 3 + cc];
                // nearest-2x: row map {0,1,1,2}, col map {0,1,1,2,2,3}
#pragma unroll
                for (int j = 0; j < 6; j++) {
                    const int cc = (j + 1) >> 1;
                    rv[0][j] = s[0][cc];
                    rv[1][j] = s[1][cc];
                    rv[2][j] = s[1][cc];
                    rv[3][j] = s[2][cc];
                }
            }
            const ulonglong2* wsc = (const ulonglong2*)(wall +
                ((CIN > 64) ? ((i * CIB + ci_l) & 63) : (i * CIB + ci_l)) * 36);
#pragma unroll
            for (int ky = 0; ky < 3; ky++) {
#pragma unroll
                for (int kx = 0; kx < 3; kx++) {
                    const int k = ky * 3 + kx;
                    ulonglong2 wA = wsc[k * 2];
                    ulonglong2 wB = wsc[k * 2 + 1];
#pragma unroll
                    for (int py = 0; py < 2; py++) {
#pragma unroll
                        for (int px = 0; px < 4; px++) {
                            float v = rv[py + ky][px + kx];
                            ULL vv = pack2(v, v);
                            acc[py][px][0] = fma2(vv, wA.x, acc[py][px][0]);
                            acc[py][px][1] = fma2(vv, wA.y, acc[py][px][1]);
                            acc[py][px][2] = fma2(vv, wB.x, acc[py][px][2]);
                            acc[py][px][3] = fma2(vv, wB.y, acc[py][px][3]);
                        }
                    }
                }
            }
        }
    }

    // fused 1x1-conv skip, 8 cs channels per sync round, float4 staging
    if (SKIP == 2) {
        __syncthreads();   // release tile buffers from last compute round
        float4* tiles4 = (float4*)tiles;
#pragma unroll 1
        for (int cs0 = 0; cs0 < CSKIP; cs0 += 8) {
#pragma unroll
            for (int cs_l = 0; cs_l < 8; cs_l++) {
                const float4* sp4 = (const float4*)(skip_in
                    + ((b * CSKIP + cs0 + cs_l) * OH + blockIdx.y * 32) * OW
                    + blockIdx.x * 64);
#pragma unroll
                for (int j = 0; j < 2; j++) {
                    int f = t + 256 * j;            // 512 float4 per channel
                    int row = f >> 4, c4 = f & 15;
                    tiles4[cs_l * 512 + f] = sp4[row * (OW >> 2) + c4];
                }
            }
            if (t < 32) {
                int cs_l = t >> 2, p = t & 3;
                int ca = co0 + 2 * p;
                float wa = (ca < COUT) ? skip_w[ca * CSKIP + cs0 + cs_l] : 0.f;
                float wb = (ca + 1 < COUT) ? skip_w[(ca + 1) * CSKIP + cs0 + cs_l] : 0.f;
                wall[t] = pack2(wa, wb);
            }
            __syncthreads();
#pragma unroll
            for (int cs_l = 0; cs_l < 8; cs_l++) {
                ulonglong2 wA = ((const ulonglong2*)wall)[cs_l * 2];
                ulonglong2 wB = ((const ulonglong2*)wall)[cs_l * 2 + 1];
#pragma unroll
                for (int py = 0; py < 2; py++) {
                    float4 s4 = *(const float4*)&tiles[cs_l * 2048 + (2 * ty + py) * 64 + 4 * tx];
                    float sv[4] = {s4.x, s4.y, s4.z, s4.w};
#pragma unroll
                    for (int px = 0; px < 4; px++) {
                        ULL vv = pack2(sv[px], sv[px]);
                        acc[py][px][0] = fma2(vv, wA.x, acc[py][px][0]);
                        acc[py][px][1] = fma2(vv, wA.y, acc[py][px][1]);
                        acc[py][px][2] = fma2(vv, wB.x, acc[py][px][2]);
                        acc[py][px][3] = fma2(vv, wB.y, acc[py][px][3]);
                    }
                }
            }
            __syncthreads();
        }
    }

    // epilogue: bias (+skip) (+relu), float4 stores
    float bv[8];
#pragma unroll
    for (int c = 0; c < 8; c++) bv[c] = (co0 + c < COUT) ? bias[co0 + c] : 0.f;

#pragma unroll
    for (int c = 0; c < 8; c++) {
        const int co = co0 + c;
        if (co < COUT) {
            const int p = c >> 1, hi = c & 1;
#pragma unroll
            for (int py = 0; py < 2; py++) {
                float o[4];
#pragma unroll
                for (int px = 0; px < 4; px++) {
                    float a0, a1;
                    unpack2(acc[py][px][p], a0, a1);
                    o[px] = (hi ? a1 : a0) + bv[c];
                }
                const int base = ((b * COUT + co) * OH + oy0 + py) * OW + ox0;
                if (SKIP == 1) {
                    float4 s = *(const float4*)&skip_in[base];
                    o[0] += s.x; o[1] += s.y; o[2] += s.z; o[3] += s.w;
                }
                if (SKIP == 2) {
                    float sb = skip_b[co];
#pragma unroll
                    for (int px = 0; px < 4; px++) o[px] += sb;
                }
                if (RELU) {
#pragma unroll
                    for (int px = 0; px < 4; px++) o[px] = fmaxf(o[px], 0.f);
                }
                float4 ov; ov.x = o[0]; ov.y = o[1]; ov.z = o[2]; ov.w = o[3];
                *(float4*)&out[base] = ov;
            }
        }
    }
}

// ---------------------------------------------------------------------------
// Stride-2 conv (relu, no skip), single-barrier cp.async pipeline.
// Block: 256 threads -> 32x32 output tile, 8 outch. Thread: 2x2 px.
// Tile: 65 rows x 72-float stride, frame col0 <-> gx = blkX*64 - 4.
// ---------------------------------------------------------------------------
template <int CIN, int CIB>
__global__ void __launch_bounds__(256, 2) conv3x3s2_k(
    const float* __restrict__ in, const float* __restrict__ wgt,
    const float* __restrict__ bias, float* __restrict__ out,
    int IH, int IW, int OH, int OW, int COUT, int nG)
{
    constexpr int WCI = (CIN > 64) ? 64 : CIN;
    extern __shared__ __align__(16) char smem_raw[];
    float* tiles = (float*)smem_raw;                                   // 2*CIB*4680
    ULL* wall = (ULL*)(smem_raw + 2 * CIB * 4680 * sizeof(float));     // WCI*36

    const int t = threadIdx.x;
    const int tx = t & 15, ty = t >> 4;
    const int b = blockIdx.z / nG;
    const int co0 = (blockIdx.z - b * nG) * 8;
    const int ox0 = blockIdx.x * 32;
    const int oy0 = blockIdx.y * 32;
    const int x0a = blockIdx.x * 64 - 4;
    const int y0 = blockIdx.y * 64 - 1;

    const unsigned tiles_s = (unsigned)__cvta_generic_to_shared(tiles);

    auto stage = [&](int ci0, int buf) {
        unsigned tb = tiles_s + buf * (CIB * 4680 * 4);
        constexpr int NCH = CIB * 1170;   // 65 rows x 18 chunks
#pragma unroll
        for (int j = 0; j < (NCH + 255) / 256; j++) {
            int e = t + 256 * j;
            if (e < NCH) {
                int ci_l = e / 1170, rem = e - ci_l * 1170;
                int row = rem / 18, c16 = rem - row * 18;
                int gy = y0 + row;
                int gx = x0a + 4 * c16;
                bool v = (unsigned)gy < (unsigned)IH && (unsigned)gx < (unsigned)IW;
                const float* inc = in + (b * CIN + ci0 + ci_l) * (IH * IW);
                const float* sp = inc + (v ? (gy * IW + gx) : 0);
                cpa16(tb + (ci_l * 4680 + row * 72 + 4 * c16) * 4, sp, v);
            }
        }
        cp_commit();
    };

    auto load_wall = [&](int cbase) {
        for (int e = t; e < WCI * 36; e += 256) {
            int ci_l = e / 36, r = e - ci_l * 36;
            int k = r >> 2, p = r & 3;
            int ca = co0 + 2 * p;
            int ci = cbase + ci_l;
            float wa = (ca < COUT) ? wgt[(ca * CIN + ci) * 9 + k] : 0.f;
            float wb = (ca + 1 < COUT) ? wgt[((ca + 1) * CIN + ci) * 9 + k] : 0.f;
            wall[e] = pack2(wa, wb);
        }
    };

    ULL acc[2][2][4];
#pragma unroll
    for (int py = 0; py < 2; py++)
#pragma unroll
        for (int px = 0; px < 2; px++)
#pragma unroll
            for (int p = 0; p < 4; p++) acc[py][px][p] = 0ull;

    constexpr int NR = CIN / CIB;
    stage(0, 0);
    load_wall(0);

#pragma unroll 1
    for (int i = 0; i < NR; i++) {
        cp_wait<0>();
        __syncthreads();
        if (CIN > WCI && i * CIB == WCI) {
            load_wall(WCI);
            __syncthreads();
        }
        if (i + 1 < NR) stage((i + 1) * CIB, (i + 1) & 1);
        const float* tbuf = tiles + (i & 1) * (CIB * 4680);
#pragma unroll
        for (int ci_l = 0; ci_l < CIB; ci_l++) {
            const float* tci = tbuf + ci_l * 4680;
            float rv[5][5];
#pragma unroll
            for (int r = 0; r < 5; r++) {
                const float* p = &tci[(4 * ty + r) * 72 + 4 * tx];
                float4 a = *(const float4*)p;
                float4 b4 = *(const float4*)(p + 4);
                rv[r][0] = a.w;
                rv[r][1] = b4.x; rv[r][2] = b4.y; rv[r][3] = b4.z; rv[r][4] = b4.w;
            }
            const ulonglong2* wsc = (const ulonglong2*)(wall +
                ((CIN > 64) ? ((i * CIB + ci_l) & 63) : (i * CIB + ci_l)) * 36);
#pragma unroll
            for (int ky = 0; ky < 3; ky++) {
#pragma unroll
                for (int kx = 0; kx < 3; kx++) {
                    const int k = ky * 3 + kx;
                    ulonglong2 wA = wsc[k * 2];
                    ulonglong2 wB = wsc[k * 2 + 1];
#pragma unroll
                    for (int py = 0; py < 2; py++) {
#pragma unroll
                        for (int px = 0; px < 2; px++) {
                            float v = rv[2 * py + ky][2 * px + kx];
                            ULL vv = pack2(v, v);
                            acc[py][px][0] = fma2(vv, wA.x, acc[py][px][0]);
                            acc[py][px][1] = fma2(vv, wA.y, acc[py][px][1]);
                            acc[py][px][2] = fma2(vv, wB.x, acc[py][px][2]);
                            acc[py][px][3] = fma2(vv, wB.y, acc[py][px][3]);
                        }
                    }
                }
            }
        }
    }

#pragma unroll
    for (int c = 0; c < 8; c++) {
        const int co = co0 + c;
        if (co < COUT) {
            const float bb = bias[co];
            const int p = c >> 1, hi = c & 1;
#pragma unroll
            for (int py = 0; py < 2; py++) {
                float o[2];
#pragma unroll
                for (int px = 0; px < 2; px++) {
                    float a0, a1;
                    unpack2(acc[py][px][p], a0, a1);
                    o[px] = fmaxf((hi ? a1 : a0) + bb, 0.f);
                }
                float2 ov; ov.x = o[0]; ov.y = o[1];
                *(float2*)&out[((b * COUT + co) * OH + oy0 + 2 * ty + py) * OW
                               + ox0 + 2 * tx] = ov;
            }
        }
    }
}

// ---------------------------------------------------------------------------
// XLA-style warp row reduction of sum(x*x) over 128 elements.
// ---------------------------------------------------------------------------
__device__ __forceinline__ float warp_sumsq_128(const float* __restrict__ x, int lane)
{
    float s = 0.f;
#pragma unroll
    for (int i = 0; i < 4; i++) {
        float v = x[lane + 32 * i];
        s = __fadd_rn(s, __fmul_rn(v, v));
    }
#pragma unroll
    for (int off = 16; off > 0; off >>= 1)
        s = __fadd_rn(s, __shfl_down_sync(0xffffffffu, s, off));
    return s;
}

__global__ void __launch_bounds__(256) prep_cnorm_k(const float* __restrict__ cb)
{
    if (blockIdx.x == 0 && threadIdx.x == 0) g_loss = 0.0;
    int warp = (blockIdx.x * 256 + threadIdx.x) >> 5;
    int lane = threadIdx.x & 31;
    if (warp < 1024) {
        float s = warp_sumsq_128(cb + warp * 128, lane);
        if (lane == 0) g_cnorm[warp] = s;
    }
}

__global__ void __launch_bounds__(256) transpose_cb_k(const float* __restrict__ cb)
{
    int i = blockIdx.x * 256 + threadIdx.x;
    int code = i >> 7, k = i & 127;
    g_cbT[k * 1024 + code] = cb[i];
}

// ---------------------------------------------------------------------------
// Quantizer (unchanged — arithmetic is load-bearing):
// d = fl( fl(znorm - 2*dot) + cnorm ), sequential-k fp32 FMA chains,
// lexicographic argmin, straight-through fl(z + fl(q - z)).
// ---------------------------------------------------------------------------
__global__ void __launch_bounds__(256) quantize_k(
    const float* __restrict__ z, const float* __restrict__ cb,
    float* __restrict__ qst)
{
    __shared__ float ct[8 * 1024];
    __shared__ float zs[16 * 128];
    __shared__ float znorm_s[16];
    __shared__ float cand_d[16][8];
    __shared__ int   cand_i[16][8];
    __shared__ int   kbest_s[16];
    __shared__ double red[256];

    const int t = threadIdx.x;
    const int lane = t & 31, w = t >> 5;
    const long long row0 = (long long)blockIdx.x * 16;

    {
        const float4* zg = (const float4*)(z + row0 * 128);
        float4* z4 = (float4*)zs;
#pragma unroll
        for (int j = 0; j < 2; j++) z4[t + 256 * j] = zg[t + 256 * j];
    }
    __syncthreads();

#pragma unroll
    for (int rr = 0; rr < 2; rr++) {
        int r = w + 8 * rr;
        float s = warp_sumsq_128(zs + r * 128, lane);
        if (lane == 0) znorm_s[r] = s;
    }

    ULL acc[16][2];
#pragma unroll
    for (int r = 0; r < 16; r++) { acc[r][0] = 0ull; acc[r][1] = 0ull; }

#pragma unroll 1
    for (int kt = 0; kt < 16; kt++) {
        __syncthreads();
        {
            const float4* gt = (const float4*)(g_cbT + kt * 8 * 1024);
            float4* c4s = (float4*)ct;
#pragma unroll
            for (int j = 0; j < 8; j++) c4s[t + 256 * j] = gt[t + 256 * j];
        }
        __syncthreads();
#pragma unroll
        for (int kk = 0; kk < 8; kk++) {
            float4 c4 = ((const float4*)ct)[kk * 256 + t];
            ULL cab = pack2(c4.x, c4.y);
            ULL ccd = pack2(c4.z, c4.w);
            const int k = kt * 8 + kk;
#pragma unroll
            for (int r = 0; r < 16; r++) {
                float zk = zs[r * 128 + k];
                ULL zz = pack2(zk, zk);
                acc[r][0] = fma2(zz, cab, acc[r][0]);
                acc[r][1] = fma2(zz, ccd, acc[r][1]);
            }
        }
    }
    __syncthreads();

    float4 cn4 = *(const float4*)(g_cnorm + 4 * t);
#pragma unroll
    for (int r = 0; r < 16; r++) {
        float a, b, c, d;
        unpack2(acc[r][0], a, b);
        unpack2(acc[r][1], c, d);
        float zn = znorm_s[r];
        float d0 = __fadd_rn(__fsub_rn(zn, __fmul_rn(2.f, a)), cn4.x);
        float d1 = __fadd_rn(__fsub_rn(zn, __fmul_rn(2.f, b)), cn4.y);
        float d2 = __fadd_rn(__fsub_rn(zn, __fmul_rn(2.f, c)), cn4.z);
        float d3 = __fadd_rn(__fsub_rn(zn, __fmul_rn(2.f, d)), cn4.w);
        float bv = d0; int bi = 4 * t;
        if (d1 < bv) { bv = d1; bi = 4 * t + 1; }
        if (d2 < bv) { bv = d2; bi = 4 * t + 2; }
        if (d3 < bv) { bv = d3; bi = 4 * t + 3; }
#pragma unroll
        for (int off = 16; off > 0; off >>= 1) {
            float ov = __shfl_down_sync(0xffffffffu, bv, off);
            int   oi = __shfl_down_sync(0xffffffffu, bi, off);
            if (ov < bv || (ov == bv && oi < bi)) { bv = ov; bi = oi; }
        }
        if (lane == 0) { cand_d[r][w] = bv; cand_i[r][w] = bi; }
    }
    __syncthreads();
    if (t < 16) {
        float bv = cand_d[t][0]; int bi = cand_i[t][0];
#pragma unroll
        for (int j = 1; j < 8; j++) {
            float ov = cand_d[t][j]; int oi = cand_i[t][j];
            if (ov < bv || (ov == bv && oi < bi)) { bv = ov; bi = oi; }
        }
        kbest_s[t] = bi;
    }
    __syncthreads();

    double ls = 0.0;
#pragma unroll
    for (int j = 0; j < 8; j++) {
        int e = j * 256 + t;
        int r = e >> 7, col = e & 127;
        float zv = zs[r * 128 + col];
        float qv = cb[kbest_s[r] * 128 + col];
        float qz = __fsub_rn(qv, zv);
        float st = __fadd_rn(zv, qz);
        qst[(row0 + r) * 128 + col] = st;
        ls += (double)qz * (double)qz;
    }
    red[t] = ls;
    __syncthreads();
    for (int s = 128; s > 0; s >>= 1) {
        if (t < s) red[t] += red[t + s];
        __syncthreads();
    }
    if (t == 0) atomicAdd(&g_loss, red[0]);
}

__global__ void finish_k(float* __restrict__ out, int start, int total)
{
    float v = (float)(1.25 * g_loss / 16777216.0);
    for (int i = start + threadIdx.x; i < total; i += 32) out[i] = v;
}

// ---------------------------------------------------------------------------
extern "C" void kernel_launch(void* const* d_in, const int* in_sizes, int n_in,
                              void* d_out, int out_size)
{
    const float* x          = (const float*)d_in[0];
    const float* enc_in_w   = (const float*)d_in[1];
    const float* enc_in_b   = (const float*)d_in[2];
    const float* rb0_w1     = (const float*)d_in[3];
    const float* rb0_b1     = (const float*)d_in[4];
    const float* rb0_w2     = (const float*)d_in[5];
    const float* rb0_b2     = (const float*)d_in[6];
    const float* rb1_w1     = (const float*)d_in[7];
    const float* rb1_b1     = (const float*)d_in[8];
    const float* rb1_w2     = (const float*)d_in[9];
    const float* rb1_b2     = (const float*)d_in[10];
    const float* rb1_ws     = (const float*)d_in[11];
    const float* rb1_bs     = (const float*)d_in[12];
    const float* down_w     = (const float*)d_in[13];
    const float* down_b     = (const float*)d_in[14];
    const float* codebook   = (const float*)d_in[15];
    const float* d1_w1      = (const float*)d_in[16];
    const float* d1_b1      = (const float*)d_in[17];
    const float* d1_w2      = (const float*)d_in[18];
    const float* d1_b2      = (const float*)d_in[19];
    const float* up_w       = (const float*)d_in[20];
    const float* up_b       = (const float*)d_in[21];
    const float* d0_w1      = (const float*)d_in[22];
    const float* d0_b1      = (const float*)d_in[23];
    const float* d0_w2      = (const float*)d_in[24];
    const float* d0_b2      = (const float*)d_in[25];
    const float* out_w      = (const float*)d_in[26];
    const float* out_b      = (const float*)d_in[27];
    float* out = (float*)d_out;

    float *bufA, *bufB, *bufC;
    cudaGetSymbolAddress((void**)&bufA, g_bufA);
    cudaGetSymbolAddress((void**)&bufB, g_bufB);
    cudaGetSymbolAddress((void**)&bufC, g_bufC);

    // dynamic smem: tiles 2*CIB*TCI*4 + weights min(CIN,64)*36*8
    const int SM_3   = 2 * 3 * 2448 * 4 + 3 * 36 * 8;     //  59616
    const int SM_64  = 2 * 4 * 2448 * 4 + 64 * 36 * 8;    //  96768
    const int SM_128 = 2 * 4 * 2448 * 4 + 64 * 36 * 8;    //  96768
    const int SM_UP  = 2 * 4 * 720 * 4 + 64 * 36 * 8;     //  41472
    const int SM_S2  = 2 * 2 * 4680 * 4 + 64 * 36 * 8;    //  93312

    cudaFuncSetAttribute(conv3x3n_k<3, 3, false, 0, false>,  cudaFuncAttributeMaxDynamicSharedMemorySize, SM_3);
    cudaFuncSetAttribute(conv3x3n_k<64, 4, true, 0, false>,  cudaFuncAttributeMaxDynamicSharedMemorySize, SM_64);
    cudaFuncSetAttribute(conv3x3n_k<64, 4, true, 1, false>,  cudaFuncAttributeMaxDynamicSharedMemorySize, SM_64);
    cudaFuncSetAttribute(conv3x3n_k<64, 4, false, 0, false>, cudaFuncAttributeMaxDynamicSharedMemorySize, SM_64);
    cudaFuncSetAttribute(conv3x3n_k<128, 4, true, 0, false>, cudaFuncAttributeMaxDynamicSharedMemorySize, SM_128);
    cudaFuncSetAttribute(conv3x3n_k<128, 4, true, 1, false>, cudaFuncAttributeMaxDynamicSharedMemorySize, SM_128);
    cudaFuncSetAttribute(conv3x3n_k<128, 4, true, 2, false>, cudaFuncAttributeMaxDynamicSharedMemorySize, SM_128);
    cudaFuncSetAttribute(conv3x3n_k<128, 4, true, 0, true>,  cudaFuncAttributeMaxDynamicSharedMemorySize, SM_UP);
    cudaFuncSetAttribute(conv3x3s2_k<128, 2>,                cudaFuncAttributeMaxDynamicSharedMemorySize, SM_S2);

    const int B = 8;
    dim3 G256_64(4, 8, B * 8);
    dim3 G256_128(4, 8, B * 16);
    dim3 G128_128(2, 4, B * 16);
    dim3 G256_3(4, 8, B * 1);
    dim3 GS2(4, 4, B * 16);

    transpose_cb_k<<<512, 256>>>(codebook);
    prep_cnorm_k<<<128, 256>>>(codebook);

    // ---- encoder ----
    conv3x3n_k<3, 3, false, 0, false><<<G256_64, 256, SM_3>>>(
        x, enc_in_w, enc_in_b, nullptr, nullptr, nullptr, bufA,
        256, 256, 256, 256, 64, 0, 8);
    conv3x3n_k<64, 4, true, 0, false><<<G256_64, 256, SM_64>>>(
        bufA, rb0_w1, rb0_b1, nullptr, nullptr, nullptr, bufB,
        256, 256, 256, 256, 64, 0, 8);
    conv3x3n_k<64, 4, true, 1, false><<<G256_64, 256, SM_64>>>(
        bufB, rb0_w2, rb0_b2, bufA, nullptr, nullptr, bufC,
        256, 256, 256, 256, 64, 0, 8);
    conv3x3n_k<64, 4, true, 0, false><<<G256_128, 256, SM_64>>>(
        bufC, rb1_w1, rb1_b1, nullptr, nullptr, nullptr, bufA,
        256, 256, 256, 256, 128, 0, 16);
    conv3x3n_k<128, 4, true, 2, false><<<G256_128, 256, SM_128>>>(
        bufA, rb1_w2, rb1_b2, bufC, rb1_ws, rb1_bs, bufB,
        256, 256, 256, 256, 128, 64, 16);
    conv3x3s2_k<128, 2><<<GS2, 256, SM_S2>>>(
        bufB, down_w, down_b, bufC,
        256, 256, 128, 128, 128, 16);

    // ---- quantizer ----
    quantize_k<<<8192, 256>>>(bufC, codebook, bufA);

    // ---- decoder ----
    conv3x3n_k<128, 4, true, 0, false><<<G128_128, 256, SM_128>>>(
        bufA, d1_w1, d1_b1, nullptr, nullptr, nullptr, bufB,
        128, 128, 128, 128, 128, 0, 16);
    conv3x3n_k<128, 4, true, 1, false><<<G128_128, 256, SM_128>>>(
        bufB, d1_w2, d1_b2, bufA, nullptr, nullptr, bufC,
        128, 128, 128, 128, 128, 0, 16);
    conv3x3n_k<128, 4, true, 0, true><<<G256_64, 256, SM_UP>>>(
        bufC, up_w, up_b, nullptr, nullptr, nullptr, bufA,
        128, 128, 256, 256, 64, 0, 8);
    conv3x3n_k<64, 4, true, 0, false><<<G256_64, 256, SM_64>>>(
        bufA, d0_w1, d0_b1, nullptr, nullptr, nullptr, bufB,
        256, 256, 256, 256, 64, 0, 8);
    conv3x3n_k<64, 4, true, 1, false><<<G256_64, 256, SM_64>>>(
        bufB, d0_w2, d0_b2, bufA, nullptr, nullptr, bufC,
        256, 256, 256, 256, 64, 0, 8);
    conv3x3n_k<64, 4, false, 0, false><<<G256_3, 256, SM_64>>>(
        bufC, out_w, out_b, nullptr, nullptr, nullptr, out,
        256, 256, 256, 256, 3, 0, 1);

    const int recon = 8 * 3 * 256 * 256;
    if (out_size > recon) finish_k<<<1, 32>>>(out, recon, out_size);
}

// round 13
// speedup vs baseline: 1.0311x; 1.0000x over previous
#include <cuda_runtime.h>
#include <cuda_bf16.h>

// ---------------------------------------------------------------------------
// VQ-VAE forward on GB300 (sm_103a).
// R12: UPS layer staged at source resolution (vectorized 16B cp.async,
// nearest-2x duplication done in registers); fused 1x1-skip batched 8/round
// with float4 staging. FMA chain order unchanged -> bit-identical output.
// ---------------------------------------------------------------------------

#define ULL unsigned long long

__device__ __forceinline__ ULL pack2(float a, float b) {
    ULL r; asm("mov.b64 %0, {%1, %2};" : "=l"(r) : "f"(a), "f"(b)); return r;
}
__device__ __forceinline__ void unpack2(ULL v, float& a, float& b) {
    asm("mov.b64 {%0, %1}, %2;" : "=f"(a), "=f"(b) : "l"(v));
}
__device__ __forceinline__ ULL fma2(ULL a, ULL b, ULL c) {
    ULL d; asm("fma.rn.f32x2 %0, %1, %2, %3;" : "=l"(d) : "l"(a), "l"(b), "l"(c)); return d;
}

__device__ __forceinline__ void cpa16(unsigned dst, const void* src, bool v) {
    int sz = v ? 16 : 0;
    asm volatile("cp.async.cg.shared.global [%0], [%1], 16, %2;"
                 :: "r"(dst), "l"(src), "r"(sz));
}
__device__ __forceinline__ void cp_commit() {
    asm volatile("cp.async.commit_group;");
}
template <int N> __device__ __forceinline__ void cp_wait() {
    asm volatile("cp.async.wait_group %0;" :: "n"(N));
}

// Scratch buffers
__device__ float g_bufA[8 * 128 * 256 * 256];
__device__ float g_bufB[8 * 128 * 256 * 256];
__device__ float g_bufC[8 * 128 * 256 * 256];
__device__ float g_cbT[128 * 1024];
__device__ float g_cnorm[1024];
__device__ double g_loss;

// ---------------------------------------------------------------------------
// Stride-1 register-tiled conv, single-barrier cp.async pipeline.
// Block: 256 threads -> 64(w) x 32(h) tile, 8 output channels.
// Thread: 2x4 px as 32 f32x2 accumulators.
// Non-UPS tile: 34 rows x 72-float stride, frame col0 <-> gx = blkX*64 - 4.
// UPS tile: source-res, 18 rows x 40-float stride, col0 <-> ix = blkX*32 - 4;
//           duplication applied in registers at rv-load (bit-identical values).
// Weight cache: WCI = min(CIN,64) channels; 2nd half reloaded mid-loop.
// ---------------------------------------------------------------------------
template <int CIN, int CIB, bool RELU, int SKIP, bool UPS>
__global__ void __launch_bounds__(256, 2) conv3x3n_k(
    const float* __restrict__ in, const float* __restrict__ wgt,
    const float* __restrict__ bias,
    const float* __restrict__ skip_in, const float* __restrict__ skip_w,
    const float* __restrict__ skip_b,
    float* __restrict__ out,
    int IH, int IW, int OH, int OW, int COUT, int CSKIP, int nG)
{
    constexpr int WCI = (CIN > 64) ? 64 : CIN;
    constexpr int TCI = UPS ? 720 : 2448;     // floats per channel tile
    extern __shared__ __align__(16) char smem_raw[];
    float* tiles = (float*)smem_raw;                                   // 2*CIB*TCI
    ULL* wall = (ULL*)(smem_raw + 2 * CIB * TCI * sizeof(float));      // WCI*36

    const int t = threadIdx.x;
    const int tx = t & 15, ty = t >> 4;
    const int b = blockIdx.z / nG;
    const int co0 = (blockIdx.z - b * nG) * 8;
    const int ox0 = blockIdx.x * 64 + 4 * tx;
    const int oy0 = blockIdx.y * 32 + 2 * ty;
    const int x0a = blockIdx.x * 64 - 4;      // non-UPS frame origin (gx)
    const int y0 = blockIdx.y * 32 - 1;
    const int iy_base = y0 >> 1;              // UPS: source row of tile row 0
    const int ix_base = blockIdx.x * 32 - 4;  // UPS: source col of tile col 0

    const unsigned tiles_s = (unsigned)__cvta_generic_to_shared(tiles);

    auto stage = [&](int ci0, int buf) {
        unsigned tb = tiles_s + buf * (CIB * TCI * 4);
        if (!UPS) {
            constexpr int NCH = CIB * 612;    // 34 rows x 18 chunks per channel
#pragma unroll
            for (int j = 0; j < (NCH + 255) / 256; j++) {
                int e = t + 256 * j;
                if (e < NCH) {
                    int ci_l = e / 612, rem = e - ci_l * 612;
                    int row = rem / 18, c16 = rem - row * 18;
                    int gy = y0 + row;
                    int gx = x0a + 4 * c16;
                    bool v = (unsigned)gy < (unsigned)IH && (unsigned)gx < (unsigned)IW;
                    const float* inc = in + (b * CIN + ci0 + ci_l) * (IH * IW);
                    const float* sp = inc + (v ? (gy * IW + gx) : 0);
                    cpa16(tb + (ci_l * 2448 + row * 72 + 4 * c16) * 4, sp, v);
                }
            }
        } else {
            constexpr int NCH = CIB * 180;    // 18 rows x 10 chunks per channel
#pragma unroll
            for (int j = 0; j < (NCH + 255) / 256; j++) {
                int e = t + 256 * j;
                if (e < NCH) {
                    int ci_l = e / 180, rem = e - ci_l * 180;
                    int row = rem / 10, c16 = rem - row * 10;
                    int iy = iy_base + row;
                    int ix = ix_base + 4 * c16;
                    bool v = (unsigned)iy < (unsigned)IH && (unsigned)ix < (unsigned)IW;
                    const float* inc = in + (b * CIN + ci0 + ci_l) * (IH * IW);
                    const float* sp = inc + (v ? (iy * IW + ix) : 0);
                    cpa16(tb + (ci_l * 720 + row * 40 + 4 * c16) * 4, sp, v);
                }
            }
        }
        cp_commit();
    };

    auto load_wall = [&](int cbase) {
        for (int e = t; e < WCI * 36; e += 256) {
            int ci_l = e / 36, r = e - ci_l * 36;
            int k = r >> 2, p = r & 3;
            int ca = co0 + 2 * p;
            int ci = cbase + ci_l;
            float wa = (ca < COUT) ? wgt[(ca * CIN + ci) * 9 + k] : 0.f;
            float wb = (ca + 1 < COUT) ? wgt[((ca + 1) * CIN + ci) * 9 + k] : 0.f;
            wall[e] = pack2(wa, wb);
        }
    };

    ULL acc[2][4][4];
#pragma unroll
    for (int py = 0; py < 2; py++)
#pragma unroll
        for (int px = 0; px < 4; px++)
#pragma unroll
            for (int p = 0; p < 4; p++) acc[py][px][p] = 0ull;

    constexpr int NR = CIN / CIB;
    stage(0, 0);
    load_wall(0);

#pragma unroll 1
    for (int i = 0; i < NR; i++) {
        cp_wait<0>();
        __syncthreads();
        if (CIN > WCI && i * CIB == WCI) {
            load_wall(WCI);
            __syncthreads();
        }
        if (i + 1 < NR) stage((i + 1) * CIB, (i + 1) & 1);
        const float* tbuf = tiles + (i & 1) * (CIB * TCI);
#pragma unroll
        for (int ci_l = 0; ci_l < CIB; ci_l++) {
            const float* tci = tbuf + ci_l * TCI;
            // rv[r][j] <-> conv-domain gx = blk*64 - 1 + 4tx + j, gy = y0 + 2ty + r
            float rv[4][6];
            if (!UPS) {
#pragma unroll
                for (int r = 0; r < 4; r++) {
                    const float* p = &tci[(2 * ty + r) * 72 + 4 * tx];
                    float4 a = *(const float4*)p;
                    float4 b4 = *(const float4*)(p + 4);
                    rv[r][0] = a.w;
                    rv[r][1] = b4.x; rv[r][2] = b4.y; rv[r][3] = b4.z; rv[r][4] = b4.w;
                    rv[r][5] = p[8];
                }
            } else {
                // source rows ty..ty+2, source cols 2tx+3..2tx+6
                float s[3][4];
#pragma unroll
                for (int rr = 0; rr < 3; rr++)
#pragma unroll
                    for (int cc = 0; cc < 4; cc++)
                        s[rr][cc] = tci[(ty + rr) * 40 + 2 * tx + 3 + cc];
                // nearest-2x: row map {0,1,1,2}, col map {0,1,1,2,2,3}
#pragma unroll
                for (int j = 0; j < 6; j++) {
                    const int cc = (j + 1) >> 1;
                    rv[0][j] = s[0][cc];
                    rv[1][j] = s[1][cc];
                    rv[2][j] = s[1][cc];
                    rv[3][j] = s[2][cc];
                }
            }
            const ulonglong2* wsc = (const ulonglong2*)(wall +
                ((CIN > 64) ? ((i * CIB + ci_l) & 63) : (i * CIB + ci_l)) * 36);
#pragma unroll
            for (int ky = 0; ky < 3; ky++) {
#pragma unroll
                for (int kx = 0; kx < 3; kx++) {
                    const int k = ky * 3 + kx;
                    ulonglong2 wA = wsc[k * 2];
                    ulonglong2 wB = wsc[k * 2 + 1];
#pragma unroll
                    for (int py = 0; py < 2; py++) {
#pragma unroll
                        for (int px = 0; px < 4; px++) {
                            float v = rv[py + ky][px + kx];
                            ULL vv = pack2(v, v);
                            acc[py][px][0] = fma2(vv, wA.x, acc[py][px][0]);
                            acc[py][px][1] = fma2(vv, wA.y, acc[py][px][1]);
                            acc[py][px][2] = fma2(vv, wB.x, acc[py][px][2]);
                            acc[py][px][3] = fma2(vv, wB.y, acc[py][px][3]);
                        }
                    }
                }
            }
        }
    }

    // fused 1x1-conv skip, 8 cs channels per sync round, float4 staging
    if (SKIP == 2) {
        __syncthreads();   // release tile buffers from last compute round
        float4* tiles4 = (float4*)tiles;
#pragma unroll 1
        for (int cs0 = 0; cs0 < CSKIP; cs0 += 8) {
#pragma unroll
            for (int cs_l = 0; cs_l < 8; cs_l++) {
                const float4* sp4 = (const float4*)(skip_in
                    + ((b * CSKIP + cs0 + cs_l) * OH + blockIdx.y * 32) * OW
                    + blockIdx.x * 64);
#pragma unroll
                for (int j = 0; j < 2; j++) {
                    int f = t + 256 * j;            // 512 float4 per channel
                    int row = f >> 4, c4 = f & 15;
                    tiles4[cs_l * 512 + f] = sp4[row * (OW >> 2) + c4];
                }
            }
            if (t < 32) {
                int cs_l = t >> 2, p = t & 3;
                int ca = co0 + 2 * p;
                float wa = (ca < COUT) ? skip_w[ca * CSKIP + cs0 + cs_l] : 0.f;
                float wb = (ca + 1 < COUT) ? skip_w[(ca + 1) * CSKIP + cs0 + cs_l] : 0.f;
                wall[t] = pack2(wa, wb);
            }
            __syncthreads();
#pragma unroll
            for (int cs_l = 0; cs_l < 8; cs_l++) {
                ulonglong2 wA = ((const ulonglong2*)wall)[cs_l * 2];
                ulonglong2 wB = ((const ulonglong2*)wall)[cs_l * 2 + 1];
#pragma unroll
                for (int py = 0; py < 2; py++) {
                    float4 s4 = *(const float4*)&tiles[cs_l * 2048 + (2 * ty + py) * 64 + 4 * tx];
                    float sv[4] = {s4.x, s4.y, s4.z, s4.w};
#pragma unroll
                    for (int px = 0; px < 4; px++) {
                        ULL vv = pack2(sv[px], sv[px]);
                        acc[py][px][0] = fma2(vv, wA.x, acc[py][px][0]);
                        acc[py][px][1] = fma2(vv, wA.y, acc[py][px][1]);
                        acc[py][px][2] = fma2(vv, wB.x, acc[py][px][2]);
                        acc[py][px][3] = fma2(vv, wB.y, acc[py][px][3]);
                    }
                }
            }
            __syncthreads();
        }
    }

    // epilogue: bias (+skip) (+relu), float4 stores
    float bv[8];
#pragma unroll
    for (int c = 0; c < 8; c++) bv[c] = (co0 + c < COUT) ? bias[co0 + c] : 0.f;

#pragma unroll
    for (int c = 0; c < 8; c++) {
        const int co = co0 + c;
        if (co < COUT) {
            const int p = c >> 1, hi = c & 1;
#pragma unroll
            for (int py = 0; py < 2; py++) {
                float o[4];
#pragma unroll
                for (int px = 0; px < 4; px++) {
                    float a0, a1;
                    unpack2(acc[py][px][p], a0, a1);
                    o[px] = (hi ? a1 : a0) + bv[c];
                }
                const int base = ((b * COUT + co) * OH + oy0 + py) * OW + ox0;
                if (SKIP == 1) {
                    float4 s = *(const float4*)&skip_in[base];
                    o[0] += s.x; o[1] += s.y; o[2] += s.z; o[3] += s.w;
                }
                if (SKIP == 2) {
                    float sb = skip_b[co];
#pragma unroll
                    for (int px = 0; px < 4; px++) o[px] += sb;
                }
                if (RELU) {
#pragma unroll
                    for (int px = 0; px < 4; px++) o[px] = fmaxf(o[px], 0.f);
                }
                float4 ov; ov.x = o[0]; ov.y = o[1]; ov.z = o[2]; ov.w = o[3];
                *(float4*)&out[base] = ov;
            }
        }
    }
}

// ---------------------------------------------------------------------------
// Stride-2 conv (relu, no skip), single-barrier cp.async pipeline.
// Block: 256 threads -> 32x32 output tile, 8 outch. Thread: 2x2 px.
// Tile: 65 rows x 72-float stride, frame col0 <-> gx = blkX*64 - 4.
// ---------------------------------------------------------------------------
template <int CIN, int CIB>
__global__ void __launch_bounds__(256, 2) conv3x3s2_k(
    const float* __restrict__ in, const float* __restrict__ wgt,
    const float* __restrict__ bias, float* __restrict__ out,
    int IH, int IW, int OH, int OW, int COUT, int nG)
{
    constexpr int WCI = (CIN > 64) ? 64 : CIN;
    extern __shared__ __align__(16) char smem_raw[];
    float* tiles = (float*)smem_raw;                                   // 2*CIB*4680
    ULL* wall = (ULL*)(smem_raw + 2 * CIB * 4680 * sizeof(float));     // WCI*36

    const int t = threadIdx.x;
    const int tx = t & 15, ty = t >> 4;
    const int b = blockIdx.z / nG;
    const int co0 = (blockIdx.z - b * nG) * 8;
    const int ox0 = blockIdx.x * 32;
    const int oy0 = blockIdx.y * 32;
    const int x0a = blockIdx.x * 64 - 4;
    const int y0 = blockIdx.y * 64 - 1;

    const unsigned tiles_s = (unsigned)__cvta_generic_to_shared(tiles);

    auto stage = [&](int ci0, int buf) {
        unsigned tb = tiles_s + buf * (CIB * 4680 * 4);
        constexpr int NCH = CIB * 1170;   // 65 rows x 18 chunks
#pragma unroll
        for (int j = 0; j < (NCH + 255) / 256; j++) {
            int e = t + 256 * j;
            if (e < NCH) {
                int ci_l = e / 1170, rem = e - ci_l * 1170;
                int row = rem / 18, c16 = rem - row * 18;
                int gy = y0 + row;
                int gx = x0a + 4 * c16;
                bool v = (unsigned)gy < (unsigned)IH && (unsigned)gx < (unsigned)IW;
                const float* inc = in + (b * CIN + ci0 + ci_l) * (IH * IW);
                const float* sp = inc + (v ? (gy * IW + gx) : 0);
                cpa16(tb + (ci_l * 4680 + row * 72 + 4 * c16) * 4, sp, v);
            }
        }
        cp_commit();
    };

    auto load_wall = [&](int cbase) {
        for (int e = t; e < WCI * 36; e += 256) {
            int ci_l = e / 36, r = e - ci_l * 36;
            int k = r >> 2, p = r & 3;
            int ca = co0 + 2 * p;
            int ci = cbase + ci_l;
            float wa = (ca < COUT) ? wgt[(ca * CIN + ci) * 9 + k] : 0.f;
            float wb = (ca + 1 < COUT) ? wgt[((ca + 1) * CIN + ci) * 9 + k] : 0.f;
            wall[e] = pack2(wa, wb);
        }
    };

    ULL acc[2][2][4];
#pragma unroll
    for (int py = 0; py < 2; py++)
#pragma unroll
        for (int px = 0; px < 2; px++)
#pragma unroll
            for (int p = 0; p < 4; p++) acc[py][px][p] = 0ull;

    constexpr int NR = CIN / CIB;
    stage(0, 0);
    load_wall(0);

#pragma unroll 1
    for (int i = 0; i < NR; i++) {
        cp_wait<0>();
        __syncthreads();
        if (CIN > WCI && i * CIB == WCI) {
            load_wall(WCI);
            __syncthreads();
        }
        if (i + 1 < NR) stage((i + 1) * CIB, (i + 1) & 1);
        const float* tbuf = tiles + (i & 1) * (CIB * 4680);
#pragma unroll
        for (int ci_l = 0; ci_l < CIB; ci_l++) {
            const float* tci = tbuf + ci_l * 4680;
            float rv[5][5];
#pragma unroll
            for (int r = 0; r < 5; r++) {
                const float* p = &tci[(4 * ty + r) * 72 + 4 * tx];
                float4 a = *(const float4*)p;
                float4 b4 = *(const float4*)(p + 4);
                rv[r][0] = a.w;
                rv[r][1] = b4.x; rv[r][2] = b4.y; rv[r][3] = b4.z; rv[r][4] = b4.w;
            }
            const ulonglong2* wsc = (const ulonglong2*)(wall +
                ((CIN > 64) ? ((i * CIB + ci_l) & 63) : (i * CIB + ci_l)) * 36);
#pragma unroll
            for (int ky = 0; ky < 3; ky++) {
#pragma unroll
                for (int kx = 0; kx < 3; kx++) {
                    const int k = ky * 3 + kx;
                    ulonglong2 wA = wsc[k * 2];
                    ulonglong2 wB = wsc[k * 2 + 1];
#pragma unroll
                    for (int py = 0; py < 2; py++) {
#pragma unroll
                        for (int px = 0; px < 2; px++) {
                            float v = rv[2 * py + ky][2 * px + kx];
                            ULL vv = pack2(v, v);
                            acc[py][px][0] = fma2(vv, wA.x, acc[py][px][0]);
                            acc[py][px][1] = fma2(vv, wA.y, acc[py][px][1]);
                            acc[py][px][2] = fma2(vv, wB.x, acc[py][px][2]);
                            acc[py][px][3] = fma2(vv, wB.y, acc[py][px][3]);
                        }
                    }
                }
            }
        }
    }

#pragma unroll
    for (int c = 0; c < 8; c++) {
        const int co = co0 + c;
        if (co < COUT) {
            const float bb = bias[co];
            const int p = c >> 1, hi = c & 1;
#pragma unroll
            for (int py = 0; py < 2; py++) {
                float o[2];
#pragma unroll
                for (int px = 0; px < 2; px++) {
                    float a0, a1;
                    unpack2(acc[py][px][p], a0, a1);
                    o[px] = fmaxf((hi ? a1 : a0) + bb, 0.f);
                }
                float2 ov; ov.x = o[0]; ov.y = o[1];
                *(float2*)&out[((b * COUT + co) * OH + oy0 + 2 * ty + py) * OW
                               + ox0 + 2 * tx] = ov;
            }
        }
    }
}

// ---------------------------------------------------------------------------
// XLA-style warp row reduction of sum(x*x) over 128 elements.
// ---------------------------------------------------------------------------
__device__ __forceinline__ float warp_sumsq_128(const float* __restrict__ x, int lane)
{
    float s = 0.f;
#pragma unroll
    for (int i = 0; i < 4; i++) {
        float v = x[lane + 32 * i];
        s = __fadd_rn(s, __fmul_rn(v, v));
    }
#pragma unroll
    for (int off = 16; off > 0; off >>= 1)
        s = __fadd_rn(s, __shfl_down_sync(0xffffffffu, s, off));
    return s;
}

__global__ void __launch_bounds__(256) prep_cnorm_k(const float* __restrict__ cb)
{
    if (blockIdx.x == 0 && threadIdx.x == 0) g_loss = 0.0;
    int warp = (blockIdx.x * 256 + threadIdx.x) >> 5;
    int lane = threadIdx.x & 31;
    if (warp < 1024) {
        float s = warp_sumsq_128(cb + warp * 128, lane);
        if (lane == 0) g_cnorm[warp] = s;
    }
}

__global__ void __launch_bounds__(256) transpose_cb_k(const float* __restrict__ cb)
{
    int i = blockIdx.x * 256 + threadIdx.x;
    int code = i >> 7, k = i & 127;
    g_cbT[k * 1024 + code] = cb[i];
}

// ---------------------------------------------------------------------------
// Quantizer (unchanged — arithmetic is load-bearing):
// d = fl( fl(znorm - 2*dot) + cnorm ), sequential-k fp32 FMA chains,
// lexicographic argmin, straight-through fl(z + fl(q - z)).
// ---------------------------------------------------------------------------
__global__ void __launch_bounds__(256) quantize_k(
    const float* __restrict__ z, const float* __restrict__ cb,
    float* __restrict__ qst)
{
    __shared__ float ct[8 * 1024];
    __shared__ float zs[16 * 128];
    __shared__ float znorm_s[16];
    __shared__ float cand_d[16][8];
    __shared__ int   cand_i[16][8];
    __shared__ int   kbest_s[16];
    __shared__ double red[256];

    const int t = threadIdx.x;
    const int lane = t & 31, w = t >> 5;
    const long long row0 = (long long)blockIdx.x * 16;

    {
        const float4* zg = (const float4*)(z + row0 * 128);
        float4* z4 = (float4*)zs;
#pragma unroll
        for (int j = 0; j < 2; j++) z4[t + 256 * j] = zg[t + 256 * j];
    }
    __syncthreads();

#pragma unroll
    for (int rr = 0; rr < 2; rr++) {
        int r = w + 8 * rr;
        float s = warp_sumsq_128(zs + r * 128, lane);
        if (lane == 0) znorm_s[r] = s;
    }

    ULL acc[16][2];
#pragma unroll
    for (int r = 0; r < 16; r++) { acc[r][0] = 0ull; acc[r][1] = 0ull; }

#pragma unroll 1
    for (int kt = 0; kt < 16; kt++) {
        __syncthreads();
        {
            const float4* gt = (const float4*)(g_cbT + kt * 8 * 1024);
            float4* c4s = (float4*)ct;
#pragma unroll
            for (int j = 0; j < 8; j++) c4s[t + 256 * j] = gt[t + 256 * j];
        }
        __syncthreads();
#pragma unroll
        for (int kk = 0; kk < 8; kk++) {
            float4 c4 = ((const float4*)ct)[kk * 256 + t];
            ULL cab = pack2(c4.x, c4.y);
            ULL ccd = pack2(c4.z, c4.w);
            const int k = kt * 8 + kk;
#pragma unroll
            for (int r = 0; r < 16; r++) {
                float zk = zs[r * 128 + k];
                ULL zz = pack2(zk, zk);
                acc[r][0] = fma2(zz, cab, acc[r][0]);
                acc[r][1] = fma2(zz, ccd, acc[r][1]);
            }
        }
    }
    __syncthreads();

    float4 cn4 = *(const float4*)(g_cnorm + 4 * t);
#pragma unroll
    for (int r = 0; r < 16; r++) {
        float a, b, c, d;
        unpack2(acc[r][0], a, b);
        unpack2(acc[r][1], c, d);
        float zn = znorm_s[r];
        float d0 = __fadd_rn(__fsub_rn(zn, __fmul_rn(2.f, a)), cn4.x);
        float d1 = __fadd_rn(__fsub_rn(zn, __fmul_rn(2.f, b)), cn4.y);
        float d2 = __fadd_rn(__fsub_rn(zn, __fmul_rn(2.f, c)), cn4.z);
        float d3 = __fadd_rn(__fsub_rn(zn, __fmul_rn(2.f, d)), cn4.w);
        float bv = d0; int bi = 4 * t;
        if (d1 < bv) { bv = d1; bi = 4 * t + 1; }
        if (d2 < bv) { bv = d2; bi = 4 * t + 2; }
        if (d3 < bv) { bv = d3; bi = 4 * t + 3; }
#pragma unroll
        for (int off = 16; off > 0; off >>= 1) {
            float ov = __shfl_down_sync(0xffffffffu, bv, off);
            int   oi = __shfl_down_sync(0xffffffffu, bi, off);
            if (ov < bv || (ov == bv && oi < bi)) { bv = ov; bi = oi; }
        }
        if (lane == 0) { cand_d[r][w] = bv; cand_i[r][w] = bi; }
    }
    __syncthreads();
    if (t < 16) {
        float bv = cand_d[t][0]; int bi = cand_i[t][0];
#pragma unroll
        for (int j = 1; j < 8; j++) {
            float ov = cand_d[t][j]; int oi = cand_i[t][j];
            if (ov < bv || (ov == bv && oi < bi)) { bv = ov; bi = oi; }
        }
        kbest_s[t] = bi;
    }
    __syncthreads();

    double ls = 0.0;
#pragma unroll
    for (int j = 0; j < 8; j++) {
        int e = j * 256 + t;
        int r = e >> 7, col = e & 127;
        float zv = zs[r * 128 + col];
        float qv = cb[kbest_s[r] * 128 + col];
        float qz = __fsub_rn(qv, zv);
        float st = __fadd_rn(zv, qz);
        qst[(row0 + r) * 128 + col] = st;
        ls += (double)qz * (double)qz;
    }
    red[t] = ls;
    __syncthreads();
    for (int s = 128; s > 0; s >>= 1) {
        if (t < s) red[t] += red[t + s];
        __syncthreads();
    }
    if (t == 0) atomicAdd(&g_loss, red[0]);
}

__global__ void finish_k(float* __restrict__ out, int start, int total)
{
    float v = (float)(1.25 * g_loss / 16777216.0);
    for (int i = start + threadIdx.x; i < total; i += 32) out[i] = v;
}

// ---------------------------------------------------------------------------
extern "C" void kernel_launch(void* const* d_in, const int* in_sizes, int n_in,
                              void* d_out, int out_size)
{
    const float* x          = (const float*)d_in[0];
    const float* enc_in_w   = (const float*)d_in[1];
    const float* enc_in_b   = (const float*)d_in[2];
    const float* rb0_w1     = (const float*)d_in[3];
    const float* rb0_b1     = (const float*)d_in[4];
    const float* rb0_w2     = (const float*)d_in[5];
    const float* rb0_b2     = (const float*)d_in[6];
    const float* rb1_w1     = (const float*)d_in[7];
    const float* rb1_b1     = (const float*)d_in[8];
    const float* rb1_w2     = (const float*)d_in[9];
    const float* rb1_b2     = (const float*)d_in[10];
    const float* rb1_ws     = (const float*)d_in[11];
    const float* rb1_bs     = (const float*)d_in[12];
    const float* down_w     = (const float*)d_in[13];
    const float* down_b     = (const float*)d_in[14];
    const float* codebook   = (const float*)d_in[15];
    const float* d1_w1      = (const float*)d_in[16];
    const float* d1_b1      = (const float*)d_in[17];
    const float* d1_w2      = (const float*)d_in[18];
    const float* d1_b2      = (const float*)d_in[19];
    const float* up_w       = (const float*)d_in[20];
    const float* up_b       = (const float*)d_in[21];
    const float* d0_w1      = (const float*)d_in[22];
    const float* d0_b1      = (const float*)d_in[23];
    const float* d0_w2      = (const float*)d_in[24];
    const float* d0_b2      = (const float*)d_in[25];
    const float* out_w      = (const float*)d_in[26];
    const float* out_b      = (const float*)d_in[27];
    float* out = (float*)d_out;

    float *bufA, *bufB, *bufC;
    cudaGetSymbolAddress((void**)&bufA, g_bufA);
    cudaGetSymbolAddress((void**)&bufB, g_bufB);
    cudaGetSymbolAddress((void**)&bufC, g_bufC);

    // dynamic smem: tiles 2*CIB*TCI*4 + weights min(CIN,64)*36*8
    const int SM_3   = 2 * 3 * 2448 * 4 + 3 * 36 * 8;     //  59616
    const int SM_64  = 2 * 4 * 2448 * 4 + 64 * 36 * 8;    //  96768
    const int SM_128 = 2 * 4 * 2448 * 4 + 64 * 36 * 8;    //  96768
    const int SM_UP  = 2 * 4 * 720 * 4 + 64 * 36 * 8;     //  41472
    const int SM_S2  = 2 * 2 * 4680 * 4 + 64 * 36 * 8;    //  93312

    cudaFuncSetAttribute(conv3x3n_k<3, 3, false, 0, false>,  cudaFuncAttributeMaxDynamicSharedMemorySize, SM_3);
    cudaFuncSetAttribute(conv3x3n_k<64, 4, true, 0, false>,  cudaFuncAttributeMaxDynamicSharedMemorySize, SM_64);
    cudaFuncSetAttribute(conv3x3n_k<64, 4, true, 1, false>,  cudaFuncAttributeMaxDynamicSharedMemorySize, SM_64);
    cudaFuncSetAttribute(conv3x3n_k<64, 4, false, 0, false>, cudaFuncAttributeMaxDynamicSharedMemorySize, SM_64);
    cudaFuncSetAttribute(conv3x3n_k<128, 4, true, 0, false>, cudaFuncAttributeMaxDynamicSharedMemorySize, SM_128);
    cudaFuncSetAttribute(conv3x3n_k<128, 4, true, 1, false>, cudaFuncAttributeMaxDynamicSharedMemorySize, SM_128);
    cudaFuncSetAttribute(conv3x3n_k<128, 4, true, 2, false>, cudaFuncAttributeMaxDynamicSharedMemorySize, SM_128);
    cudaFuncSetAttribute(conv3x3n_k<128, 4, true, 0, true>,  cudaFuncAttributeMaxDynamicSharedMemorySize, SM_UP);
    cudaFuncSetAttribute(conv3x3s2_k<128, 2>,                cudaFuncAttributeMaxDynamicSharedMemorySize, SM_S2);

    const int B = 8;
    dim3 G256_64(4, 8, B * 8);
    dim3 G256_128(4, 8, B * 16);
    dim3 G128_128(2, 4, B * 16);
    dim3 G256_3(4, 8, B * 1);
    dim3 GS2(4, 4, B * 16);

    transpose_cb_k<<<512, 256>>>(codebook);
    prep_cnorm_k<<<128, 256>>>(codebook);

    // ---- encoder ----
    conv3x3n_k<3, 3, false, 0, false><<<G256_64, 256, SM_3>>>(
        x, enc_in_w, enc_in_b, nullptr, nullptr, nullptr, bufA,
        256, 256, 256, 256, 64, 0, 8);
    conv3x3n_k<64, 4, true, 0, false><<<G256_64, 256, SM_64>>>(
        bufA, rb0_w1, rb0_b1, nullptr, nullptr, nullptr, bufB,
        256, 256, 256, 256, 64, 0, 8);
    conv3x3n_k<64, 4, true, 1, false><<<G256_64, 256, SM_64>>>(
        bufB, rb0_w2, rb0_b2, bufA, nullptr, nullptr, bufC,
        256, 256, 256, 256, 64, 0, 8);
    conv3x3n_k<64, 4, true, 0, false><<<G256_128, 256, SM_64>>>(
        bufC, rb1_w1, rb1_b1, nullptr, nullptr, nullptr, bufA,
        256, 256, 256, 256, 128, 0, 16);
    conv3x3n_k<128, 4, true, 2, false><<<G256_128, 256, SM_128>>>(
        bufA, rb1_w2, rb1_b2, bufC, rb1_ws, rb1_bs, bufB,
        256, 256, 256, 256, 128, 64, 16);
    conv3x3s2_k<128, 2><<<GS2, 256, SM_S2>>>(
        bufB, down_w, down_b, bufC,
        256, 256, 128, 128, 128, 16);

    // ---- quantizer ----
    quantize_k<<<8192, 256>>>(bufC, codebook, bufA);

    // ---- decoder ----
    conv3x3n_k<128, 4, true, 0, false><<<G128_128, 256, SM_128>>>(
        bufA, d1_w1, d1_b1, nullptr, nullptr, nullptr, bufB,
        128, 128, 128, 128, 128, 0, 16);
    conv3x3n_k<128, 4, true, 1, false><<<G128_128, 256, SM_128>>>(
        bufB, d1_w2, d1_b2, bufA, nullptr, nullptr, bufC,
        128, 128, 128, 128, 128, 0, 16);
    conv3x3n_k<128, 4, true, 0, true><<<G256_64, 256, SM_UP>>>(
        bufC, up_w, up_b, nullptr, nullptr, nullptr, bufA,
        128, 128, 256, 256, 64, 0, 8);
    conv3x3n_k<64, 4, true, 0, false><<<G256_64, 256, SM_64>>>(
        bufA, d0_w1, d0_b1, nullptr, nullptr, nullptr, bufB,
        256, 256, 256, 256, 64, 0, 8);
    conv3x3n_k<64, 4, true, 1, false><<<G256_64, 256, SM_64>>>(
        bufB, d0_w2, d0_b2, bufA, nullptr, nullptr, bufC,
        256, 256, 256, 256, 64, 0, 8);
    conv3x3n_k<64, 4, false, 0, false><<<G256_3, 256, SM_64>>>(
        bufC, out_w, out_b, nullptr, nullptr, nullptr, out,
        256, 256, 256, 256, 3, 0, 1);

    const int recon = 8 * 3 * 256 * 256;
    if (out_size > recon) finish_k<<<1, 32>>>(out, recon, out_size);
}